// round 16
// baseline (speedup 1.0000x reference)
#include <cuda_runtime.h>
#include <cstdint>
#include <cfloat>

#define BN_EPS 1e-5f

// ======================= device global scratch =======================
__device__ double g_dsum[512], g_dsq[512];

// integer stat accumulators (zeroed by k_stats_x block 0)
__device__ int                g_c1sp[128], g_c1sn[128];
__device__ unsigned long long g_c1qp[128], g_c1qn[128];
__device__ int                g_c2sp[256], g_c2sn[256];
__device__ unsigned long long g_c2qp[256], g_c2qn[256];
__device__ int                g_c4sp[1024], g_c4sn[1024];
__device__ unsigned long long g_c4qp[1024], g_c4qn[1024];

__device__ float g_t3[18432]; __device__ int g_f3[18432];

__device__ uint4    g_W2p[256 * 9];
__device__ uint4    g_W3p[4 * 18 * 128];   // [ocquarter][k(tap*2+half)][oc_local]
__device__ unsigned g_FW0pT[576 * 1024];

__device__ signed char g_a1[128 * 31 * 31 * 128];  // pooled conv1 ints, NHWC
__device__ short       g_a2[128 * 14 * 14 * 256];  // pooled conv2 ints, NHWC
__device__ uint4       g_P2[128 * 14 * 14 * 2];    // packed signs, 256 bits/pixel
__device__ short       g_p3[128 * 18432];          // pooled conv3 ints [n][f]
__device__ unsigned    g_P3[128 * 576];            // ternary sign plane
__device__ unsigned    g_P3nz[128 * 576];          // ternary nonzero mask
__device__ short       g_b1[128 * 1024];           // fc1 ints

// ======================= helpers =======================
__device__ __forceinline__ unsigned csa_s(unsigned a, unsigned b, unsigned c) {
    return a ^ b ^ c;
}
__device__ __forceinline__ unsigned csa_c(unsigned a, unsigned b, unsigned c) {
    return (a & b) | (c & (a | b));
}
__device__ __forceinline__ uint4 xor4(uint4 a, uint4 b) {
    return make_uint4(a.x ^ b.x, a.y ^ b.y, a.z ^ b.z, a.w ^ b.w);
}

// popcount of 12 words (3 pre-XORed uint4) via CSA tree: 5 POPC instead of 12
__device__ __forceinline__ int popc12c(uint4 a, uint4 b, uint4 c) {
    unsigned s0 = csa_s(a.x, a.y, a.z), c0 = csa_c(a.x, a.y, a.z);
    unsigned s1 = csa_s(a.w, b.x, b.y), c1 = csa_c(a.w, b.x, b.y);
    unsigned s2 = csa_s(b.z, b.w, c.x), c2 = csa_c(b.z, b.w, c.x);
    unsigned s3 = csa_s(c.y, c.z, c.w), c3 = csa_c(c.y, c.z, c.w);
    unsigned S0 = csa_s(s0, s1, s2),   C4 = csa_c(s0, s1, s2);
    unsigned S5 = csa_s(c0, c1, c2),   C5 = csa_c(c0, c1, c2);
    unsigned S6 = csa_s(S5, c3, C4),   C6 = csa_c(S5, c3, C4);
    return __popc(S0) + __popc(s3) + 2 * __popc(S6) + 4 * (__popc(C5) + __popc(C6));
}

// popcount of 24 words (6 pre-XORed uint4) via CSA tree: 6 POPC instead of 24
__device__ __forceinline__ int popc24c(uint4 a, uint4 b, uint4 c, uint4 d, uint4 e, uint4 f) {
    unsigned s0 = csa_s(a.x, a.y, a.z), c0 = csa_c(a.x, a.y, a.z);
    unsigned s1 = csa_s(a.w, b.x, b.y), c1 = csa_c(a.w, b.x, b.y);
    unsigned s2 = csa_s(b.z, b.w, c.x), c2 = csa_c(b.z, b.w, c.x);
    unsigned s3 = csa_s(c.y, c.z, c.w), c3 = csa_c(c.y, c.z, c.w);
    unsigned s4 = csa_s(d.x, d.y, d.z), c4 = csa_c(d.x, d.y, d.z);
    unsigned s5 = csa_s(d.w, e.x, e.y), c5 = csa_c(d.w, e.x, e.y);
    unsigned s6 = csa_s(e.z, e.w, f.x), c6 = csa_c(e.z, e.w, f.x);
    unsigned s7 = csa_s(f.y, f.z, f.w), c7 = csa_c(f.y, f.z, f.w);
    unsigned S0 = csa_s(s0, s1, s2), C0 = csa_c(s0, s1, s2);
    unsigned S1 = csa_s(s3, s4, s5), C1 = csa_c(s3, s4, s5);
    unsigned S2 = csa_s(S0, S1, s6), C2 = csa_c(S0, S1, s6);
    unsigned A0 = csa_s(c0, c1, c2), B0 = csa_c(c0, c1, c2);
    unsigned A1 = csa_s(c3, c4, c5), B1 = csa_c(c3, c4, c5);
    unsigned A2 = csa_s(c6, c7, C0), B2 = csa_c(c6, c7, C0);
    unsigned A3 = csa_s(C1, C2, A0), B3 = csa_c(C1, C2, A0);
    unsigned A4 = csa_s(A1, A2, A3), B4 = csa_c(A1, A2, A3);
    unsigned D0 = csa_s(B0, B1, B2), E0 = csa_c(B0, B1, B2);
    unsigned D1 = csa_s(B3, B4, D0), E1 = csa_c(B3, B4, D0);
    return __popc(S2) + __popc(s7) + 2 * __popc(A4) + 4 * __popc(D1)
         + 8 * (__popc(E0) + __popc(E1));
}

__device__ __forceinline__ float preluf(float v, float a) {
    return v >= 0.0f ? v : a * v;
}

// threshold from integer pos/neg sums (exact fp64); bb==0 fast path is exact
__device__ __forceinline__ void thresh_from_sums(double sp, double sn, double qp, double qn,
                                                 double a, double N, float g, float bb,
                                                 float* t, unsigned char* f) {
    if (g != 0.0f) {
        double m = (sp + a * sn) / N;
        if (bb == 0.0f) {
            *t = (float)m;
        } else {
            double q = (qp + a * a * qn) / N;
            double var = q - m * m;
            if (var < 0.) var = 0.;
            *t = (float)(m - (double)bb * sqrt(var + (double)BN_EPS) / (double)g);
        }
        *f = (g < 0.0f) ? 1 : 0;
    } else {
        *t = (bb > 0.0f) ? -FLT_MAX : FLT_MAX;
        *f = 0;
    }
}

// ======================= layer 0: input BN stats (fp64) + counter zeroing =========
__global__ void k_stats_x(const float* __restrict__ x) {
    __shared__ double ss[256], sq[256];
    int n = blockIdx.x, c = blockIdx.y, t = threadIdx.x;
    if (n == 0 && c == 0) {
        if (t < 128) { g_c1sp[t] = 0; g_c1sn[t] = 0; g_c1qp[t] = 0; g_c1qn[t] = 0; }
        g_c2sp[t] = 0; g_c2sn[t] = 0; g_c2qp[t] = 0; g_c2qn[t] = 0;
        for (int i = t; i < 1024; i += 256) {
            g_c4sp[i] = 0; g_c4sn[i] = 0; g_c4qp[i] = 0; g_c4qn[i] = 0;
        }
    }
    const float* p = x + (n * 3 + c) * 4096;
    double s = 0., q = 0.;
    for (int i = t; i < 4096; i += 256) {
        double v = (double)p[i];
        s += v; q += v * v;
    }
    ss[t] = s; sq[t] = q;
    __syncthreads();
    for (int o = 128; o > 0; o >>= 1) {
        if (t < o) { ss[t] += ss[t + o]; sq[t] += sq[t + o]; }
        __syncthreads();
    }
    if (t == 0) { g_dsum[c * 128 + n] = ss[0]; g_dsq[c * 128 + n] = sq[0]; }
}

// ======================= conv1 (3->128, 64->62, pool->31) =======================
__global__ void __launch_bounds__(128) k_conv1(const float* __restrict__ x,
                                               const float* __restrict__ cw0,
                                               const float* __restrict__ cg0,
                                               const float* __restrict__ cb0) {
    __shared__ unsigned sW[128];
    __shared__ float stc[3];
    __shared__ int sfc[3];
    int tid = threadIdx.x;
    {
        unsigned m = 0;
        const float* wp = cw0 + tid * 27;
#pragma unroll
        for (int i = 0; i < 27; i++)
            if (wp[i] > 0.f) m |= 1u << i;
        sW[tid] = m;
    }
    if (tid < 3) {
        double s = 0., q = 0.;
        for (int b = 0; b < 128; b++) { s += g_dsum[tid * 128 + b]; q += g_dsq[tid * 128 + b]; }
        double N = 524288.0;
        double m = s / N;
        double v = q / N - m * m;
        if (v < 0.) v = 0.;
        float g = cg0[tid], bb = cb0[tid];
        if (g != 0.0f) {
            stc[tid] = (float)(m - (double)bb * sqrt(v + (double)BN_EPS) / (double)g);
            sfc[tid] = (g < 0.0f) ? 1 : 0;
        } else {
            stc[tid] = (bb > 0.0f) ? -FLT_MAX : FLT_MAX;
            sfc[tid] = 0;
        }
    }
    __syncthreads();

    int idx = blockIdx.x * 128 + tid;           // < 123008
    int n = idx / 961, r = idx % 961, py = r / 31, px = r % 31;

    unsigned m[4] = {0, 0, 0, 0};
#pragma unroll
    for (int c = 0; c < 3; c++) {
        float tc = stc[c];
        int fc = sfc[c];
        const float2* xp2 = (const float2*)(x + ((n * 3 + c) * 64 + 2 * py) * 64 + 2 * px);
#pragma unroll
        for (int rr = 0; rr < 4; rr++) {
            float2 ab = xp2[rr * 32];
            float2 cd = xp2[rr * 32 + 1];
            float vv[4] = {ab.x, ab.y, cd.x, cd.y};
#pragma unroll
            for (int cc = 0; cc < 4; cc++) {
                unsigned b = ((vv[cc] > tc) != (fc != 0)) ? 1u : 0u;
#pragma unroll
                for (int dy = 0; dy < 2; dy++) {
#pragma unroll
                    for (int dx = 0; dx < 2; dx++) {
                        int ky = rr - dy, kx = cc - dx;
                        if (ky >= 0 && ky < 3 && kx >= 0 && kx < 3)
                            m[dy * 2 + dx] |= b << (c * 9 + ky * 3 + kx);
                    }
                }
            }
        }
    }
    unsigned* outw = reinterpret_cast<unsigned*>(g_a1) + (size_t)idx * 32;
#pragma unroll 4
    for (int oc4 = 0; oc4 < 32; oc4++) {
        unsigned pk = 0;
#pragma unroll
        for (int s = 0; s < 4; s++) {
            unsigned wv = sW[oc4 * 4 + s];
            int p0 = __popc(m[0] ^ wv), p1 = __popc(m[1] ^ wv);
            int p2 = __popc(m[2] ^ wv), p3 = __popc(m[3] ^ wv);
            int mn = min(min(p0, p1), min(p2, p3));
            int p = 27 - 2 * mn;
            pk |= ((unsigned)(unsigned char)(signed char)p) << (8 * s);
        }
        outw[oc4] = pk;
    }
}

// ======== stats over a1 (atomic to global) fused with pack_w2 =========
__global__ void __launch_bounds__(256) k_stats1_w2(const float* __restrict__ cw1) {
    if (blockIdx.x >= 128) {
        int tap = blockIdx.x - 128;        // 0..8
        int oc = threadIdx.x;              // 0..255
        int ky = tap / 3, kx = tap % 3;
        unsigned v[4] = {0, 0, 0, 0};
        for (int c = 0; c < 128; c++)
            if (cw1[((oc * 128 + c) * 3 + ky) * 3 + kx] > 0.f) v[c >> 5] |= 1u << (c & 31);
        g_W2p[oc * 9 + tap] = make_uint4(v[0], v[1], v[2], v[3]);
        return;
    }
    __shared__ int ssp[128], ssn[128], sqp[128], sqn[128];
    int tid = threadIdx.x, b = blockIdx.x;
    if (tid < 128) { ssp[tid] = 0; ssn[tid] = 0; sqp[tid] = 0; sqn[tid] = 0; }
    __syncthreads();
    int c4 = tid & 31, h = tid >> 5;
    const unsigned* aw = reinterpret_cast<const unsigned*>(g_a1);
    int sp[4] = {0,0,0,0}, sn[4] = {0,0,0,0}, qp[4] = {0,0,0,0}, qn[4] = {0,0,0,0};
    for (int i = h; i < 961; i += 8) {
        unsigned wd = aw[(size_t)(b * 961 + i) * 32 + c4];
#pragma unroll
        for (int k = 0; k < 4; k++) {
            int p = (int)(signed char)(wd >> (8 * k));
            int q = p * p;
            if (p >= 0) { sp[k] += p; qp[k] += q; }
            else        { sn[k] += p; qn[k] += q; }
        }
    }
#pragma unroll
    for (int k = 0; k < 4; k++) {
        atomicAdd(&ssp[c4 * 4 + k], sp[k]);
        atomicAdd(&ssn[c4 * 4 + k], sn[k]);
        atomicAdd(&sqp[c4 * 4 + k], qp[k]);
        atomicAdd(&sqn[c4 * 4 + k], qn[k]);
    }
    __syncthreads();
    if (tid < 128) {
        atomicAdd(&g_c1sp[tid], ssp[tid]);
        atomicAdd(&g_c1sn[tid], ssn[tid]);
        atomicAdd(&g_c1qp[tid], (unsigned long long)sqp[tid]);
        atomicAdd(&g_c1qn[tid], (unsigned long long)sqn[tid]);
    }
}

// ====== conv2 (128->256), pack fused, CSA popcount, stats2 epilogue fused ======
#define C2ROW(A0, A1, WB) \
    A0 += popc12c(xor4(t0, w[WB]), xor4(t1, w[(WB)+1]), xor4(t2, w[(WB)+2])); \
    A1 += popc12c(xor4(t1, w[WB]), xor4(t2, w[(WB)+1]), xor4(t3, w[(WB)+2]));
#define C2LOAD(RR) \
    t0 = sIn[RR][base]; t1 = sIn[RR][base+1]; t2 = sIn[RR][base+2]; t3 = sIn[RR][base+3];

__global__ void __launch_bounds__(256, 3) k_conv2f(const float* __restrict__ cp0,
                                                   const float* __restrict__ cg1,
                                                   const float* __restrict__ cb1) {
    __shared__ uint4 sIn[4][31];
    __shared__ float st[128];
    __shared__ unsigned char sfl[128];
    int py = blockIdx.x, n = blockIdx.y, tid = threadIdx.x;
    float a = cp0[0];
    if (tid < 128) {
        thresh_from_sums((double)g_c1sp[tid], (double)g_c1sn[tid],
                         (double)g_c1qp[tid], (double)g_c1qn[tid],
                         (double)a, 123008.0, cg1[tid], cb1[tid], &st[tid], &sfl[tid]);
    }
    unsigned* sw = reinterpret_cast<unsigned*>(sIn);
    for (int i = tid; i < 496; i += 256) sw[i] = 0;
    __syncthreads();

    const unsigned* aw = reinterpret_cast<const unsigned*>(g_a1);
    for (int i = tid; i < 124 * 32; i += 256) {
        int p = i >> 5, wv = i & 31;
        int r = p / 31, cc = p % 31;
        unsigned wd = aw[(size_t)((n * 31 + 2 * py + r) * 31 + cc) * 32 + wv];
        unsigned bits = 0;
#pragma unroll
        for (int k = 0; k < 4; k++) {
            int c = wv * 4 + k;
            float v = preluf((float)(signed char)(wd >> (8 * k)), a);
            if ((v > st[c]) != (sfl[c] != 0)) bits |= 1u << k;
        }
        atomicOr(&sw[(r * 31 + cc) * 4 + (wv >> 3)], bits << ((wv & 7) * 4));
    }
    uint4 w[9];
#pragma unroll
    for (int k = 0; k < 9; k++) w[k] = g_W2p[tid * 9 + k];
    __syncthreads();

    short* op = g_a2 + (size_t)((n * 14 + py) * 14) * 256 + tid;
    int lsp = 0, lsn = 0, lqp = 0, lqn = 0;
    for (int px = 0; px < 14; px++) {
        int base = 2 * px;
        int a00 = 0, a01 = 0, a10 = 0, a11 = 0;
        uint4 t0, t1, t2, t3;
        C2LOAD(0); C2ROW(a00, a01, 0);
        C2LOAD(1); C2ROW(a00, a01, 3); C2ROW(a10, a11, 0);
        C2LOAD(2); C2ROW(a00, a01, 6); C2ROW(a10, a11, 3);
        C2LOAD(3); C2ROW(a10, a11, 6);
        int best = min(min(a00, a01), min(a10, a11));
        int v = 1152 - 2 * best;
        op[px * 256] = (short)v;
        int q = v * v;
        if (v >= 0) { lsp += v; lqp += q; } else { lsn += v; lqn += q; }
    }
    atomicAdd(&g_c2sp[tid], lsp);
    atomicAdd(&g_c2sn[tid], lsn);
    atomicAdd(&g_c2qp[tid], (unsigned long long)lqp);
    atomicAdd(&g_c2qn[tid], (unsigned long long)lqn);
}

// ========== pack a2 -> P2 (shared transpose, coalesced) + pack_w3 rider ==========
__global__ void __launch_bounds__(128) k_pack2(const float* __restrict__ cp1,
                                               const float* __restrict__ cg2,
                                               const float* __restrict__ cb2,
                                               const float* __restrict__ cw2) {
    if (blockIdx.x >= 392) {
        int vb = blockIdx.x - 392;        // 0..35
        int tap = vb % 9, zq = vb / 9;    // zq 0..3
        int oc = zq * 128 + threadIdx.x;
        int ky = tap / 3, kx = tap % 3;
        for (int h = 0; h < 2; h++) {
            unsigned v[4] = {0, 0, 0, 0};
            for (int i = 0; i < 128; i++) {
                int c = h * 128 + i;
                if (cw2[((oc * 256 + c) * 3 + ky) * 3 + kx] > 0.f) v[i >> 5] |= 1u << (i & 31);
            }
            g_W3p[(zq * 18 + (tap * 2 + h)) * 128 + threadIdx.x] =
                make_uint4(v[0], v[1], v[2], v[3]);
        }
        return;
    }
    __shared__ unsigned sh[64][129];
    __shared__ float st[256];
    __shared__ unsigned char sfl[256];
    int tid = threadIdx.x;
    float a = cp1[0];
    {
        double ad = (double)a;
        for (int j = tid; j < 256; j += 128) {
            thresh_from_sums((double)g_c2sp[j], (double)g_c2sn[j],
                             (double)g_c2qp[j], (double)g_c2qn[j],
                             ad, 25088.0, cg2[j], cb2[j], &st[j], &sfl[j]);
        }
    }
    const unsigned* aw = reinterpret_cast<const unsigned*>(g_a2);
    size_t base = (size_t)blockIdx.x * 64 * 128;
    for (int j = tid; j < 8192; j += 128) sh[j >> 7][j & 127] = aw[base + j];
    __syncthreads();
    int pix = tid & 63, half = tid >> 6;
    unsigned wout[4];
#pragma unroll
    for (int oj = 0; oj < 4; oj++) {
        unsigned wd = 0;
#pragma unroll
        for (int i = 0; i < 32; i++) {
            int ch = half * 128 + oj * 32 + i;
            unsigned word = sh[pix][ch >> 1];
            int p = (ch & 1) ? (int)(short)(word >> 16) : (int)(short)(word & 0xFFFFu);
            float v = preluf((float)p, a);
            unsigned bit = ((v > st[ch]) != (sfl[ch] != 0)) ? 1u : 0u;
            wd |= bit << i;
        }
        wout[oj] = wd;
    }
    g_P2[((size_t)blockIdx.x * 64 + pix) * 2 + half] =
        make_uint4(wout[0], wout[1], wout[2], wout[3]);
}

// ====== conv3 (256->512), px-split + reg-capped for occupancy, reads packed P2 ====
// grid (12 = py*2+pxh, 128 n, 4 oc-quarters), 128 threads
__global__ void __launch_bounds__(128, 10) k_conv3f() {
    __shared__ uint4 sIn[4][14][2];
    int pyh = blockIdx.x, n = blockIdx.y, zq = blockIdx.z, tid = threadIdx.x;
    int py = pyh >> 1, pxh = pyh & 1;
    int oc = zq * 128 + tid;
    for (int i = tid; i < 112; i += 128) {
        int h = i & 1, t_ = i >> 1;
        int r = t_ / 14, cc = t_ % 14;
        sIn[r][cc][h] = g_P2[((n * 14 + 2 * py + r) * 14 + cc) * 2 + h];
    }
    __syncthreads();

    int A00[3] = {0,0,0}, A01[3] = {0,0,0};
    int A10[3] = {0,0,0}, A11[3] = {0,0,0};

#pragma unroll
    for (int ky = 0; ky < 3; ky++) {
        uint4 w0a = g_W3p[(zq * 18 + (ky * 3 + 0) * 2 + 0) * 128 + tid];
        uint4 w0b = g_W3p[(zq * 18 + (ky * 3 + 0) * 2 + 1) * 128 + tid];
        uint4 w1a = g_W3p[(zq * 18 + (ky * 3 + 1) * 2 + 0) * 128 + tid];
        uint4 w1b = g_W3p[(zq * 18 + (ky * 3 + 1) * 2 + 1) * 128 + tid];
        uint4 w2a = g_W3p[(zq * 18 + (ky * 3 + 2) * 2 + 0) * 128 + tid];
        uint4 w2b = g_W3p[(zq * 18 + (ky * 3 + 2) * 2 + 1) * 128 + tid];
#pragma unroll
        for (int j = 0; j < 3; j++) {
            int base = 2 * (pxh * 3 + j);
            uint4 t0a, t0b, t1a, t1b, t2a, t2b, t3a, t3b;
            t0a = sIn[ky][base][0];     t0b = sIn[ky][base][1];
            t1a = sIn[ky][base + 1][0]; t1b = sIn[ky][base + 1][1];
            t2a = sIn[ky][base + 2][0]; t2b = sIn[ky][base + 2][1];
            t3a = sIn[ky][base + 3][0]; t3b = sIn[ky][base + 3][1];
            A00[j] += popc24c(xor4(t0a, w0a), xor4(t0b, w0b),
                              xor4(t1a, w1a), xor4(t1b, w1b),
                              xor4(t2a, w2a), xor4(t2b, w2b));
            A01[j] += popc24c(xor4(t1a, w0a), xor4(t1b, w0b),
                              xor4(t2a, w1a), xor4(t2b, w1b),
                              xor4(t3a, w2a), xor4(t3b, w2b));
            t0a = sIn[ky + 1][base][0];     t0b = sIn[ky + 1][base][1];
            t1a = sIn[ky + 1][base + 1][0]; t1b = sIn[ky + 1][base + 1][1];
            t2a = sIn[ky + 1][base + 2][0]; t2b = sIn[ky + 1][base + 2][1];
            t3a = sIn[ky + 1][base + 3][0]; t3b = sIn[ky + 1][base + 3][1];
            A10[j] += popc24c(xor4(t0a, w0a), xor4(t0b, w0b),
                              xor4(t1a, w1a), xor4(t1b, w1b),
                              xor4(t2a, w2a), xor4(t2b, w2b));
            A11[j] += popc24c(xor4(t1a, w0a), xor4(t1b, w0b),
                              xor4(t2a, w1a), xor4(t2b, w1b),
                              xor4(t3a, w2a), xor4(t3b, w2b));
        }
    }

    short* op = g_p3 + (size_t)n * 18432 + oc * 36 + py * 6 + pxh * 3;
#pragma unroll
    for (int j = 0; j < 3; j++) {
        int best = min(min(A00[j], A01[j]), min(A10[j], A11[j]));
        op[j] = (short)(2304 - 2 * best);
    }
}

// ======== BN1d stats over p3 (coalesced) fused with pack_fw0 =========
__global__ void __launch_bounds__(256) k_stats3_fw0(const float* __restrict__ cp2,
                                                    const float* __restrict__ fg,
                                                    const float* __restrict__ fb,
                                                    const float* __restrict__ fw0) {
    if (blockIdx.x >= 288) {
        int id = (blockIdx.x - 288) * 256 + threadIdx.x;   // < 589824
        int j = id / 576, w = id % 576;
        const float* src = fw0 + j * 18432 + w * 32;
        unsigned v = 0;
#pragma unroll
        for (int i = 0; i < 32; i++)
            if (src[i] > 0.f) v |= 1u << i;
        g_FW0pT[w * 1024 + j] = v;
        return;
    }
    __shared__ float ss[4][64], sq2[4][64];
    int tid = threadIdx.x;
    int f0 = blockIdx.x * 64;
    int fl = tid & 63, nq = tid >> 6;
    float a = cp2[0];
    float s = 0.f, q = 0.f;
    for (int n = nq; n < 128; n += 4) {
        float v = preluf((float)g_p3[(size_t)n * 18432 + f0 + fl], a);
        s += v; q += v * v;
    }
    ss[nq][fl] = s; sq2[nq][fl] = q;
    __syncthreads();
    if (tid < 64) {
        int f = f0 + tid;
        s = ss[0][tid] + ss[1][tid] + ss[2][tid] + ss[3][tid];
        q = sq2[0][tid] + sq2[1][tid] + sq2[2][tid] + sq2[3][tid];
        float m = s / 128.f;
        float var = q / 128.f - m * m;
        var = fmaxf(var, 0.0f);
        float g = fg[f], bb = fb[f];
        if (g != 0.0f) {
            g_t3[f] = (bb == 0.0f) ? m : (m - bb * sqrtf(var + BN_EPS) / g);
            g_f3[f] = (g < 0.0f) ? 1 : 0;
        } else { g_t3[f] = (bb > 0.0f) ? -FLT_MAX : FLT_MAX; g_f3[f] = 0; }
    }
}

// ternary pack: tie (val == t) -> nz bit cleared
__global__ void k_pack3(const float* __restrict__ cp2) {
    int id = blockIdx.x * 256 + threadIdx.x;  // < 73728
    int n = id / 576, w = id % 576;
    float a = cp2[0];
    const short* src = g_p3 + (size_t)n * 18432 + w * 32;
    unsigned v = 0, nz = 0;
#pragma unroll
    for (int i = 0; i < 32; i++) {
        float val = (float)src[i];
        val = preluf(val, a);
        float t = g_t3[w * 32 + i];
        if (val != t) {
            nz |= 1u << i;
            if ((val > t) != (g_f3[w * 32 + i] != 0)) v |= 1u << i;
        }
    }
    g_P3[n * 576 + w] = v;
    g_P3nz[n * 576 + w] = nz;
}

// ============= FC1 (18432 -> 1024), ternary-aware, + stats4 epilogue =============
__global__ void __launch_bounds__(512) k_fc1() {
    __shared__ unsigned sS[2][576], sN[2][576];
    __shared__ int sK[2];
    int tid = threadIdx.x;
    int n0 = blockIdx.y * 2;
    int jn = blockIdx.x * 512 + tid;
    if (tid < 2) sK[tid] = 0;
    __syncthreads();
    for (int j = tid; j < 1152; j += 512) {
        int s = (j >= 576) ? 1 : 0;
        int w = j - s * 576;
        unsigned sg = g_P3[(n0 + s) * 576 + w];
        unsigned nz = g_P3nz[(n0 + s) * 576 + w];
        sS[s][w] = sg; sN[s][w] = nz;
        atomicAdd(&sK[s], __popc(nz));
    }
    __syncthreads();
    int a0 = 0, a1 = 0;
#pragma unroll 8
    for (int w = 0; w < 576; w++) {
        unsigned wt = g_FW0pT[w * 1024 + jn];
        a0 += __popc((sS[0][w] ^ wt) & sN[0][w]);
        a1 += __popc((sS[1][w] ^ wt) & sN[1][w]);
    }
    int v0 = sK[0] - 2 * a0;
    int v1 = sK[1] - 2 * a1;
    g_b1[n0 * 1024 + jn] = (short)v0;
    g_b1[(n0 + 1) * 1024 + jn] = (short)v1;
    unsigned long long q0 = (unsigned long long)((long long)v0 * v0);
    unsigned long long q1 = (unsigned long long)((long long)v1 * v1);
    if (v0 >= 0) { atomicAdd(&g_c4sp[jn], v0); atomicAdd(&g_c4qp[jn], q0); }
    else         { atomicAdd(&g_c4sn[jn], v0); atomicAdd(&g_c4qn[jn], q0); }
    if (v1 >= 0) { atomicAdd(&g_c4sp[jn], v1); atomicAdd(&g_c4qp[jn], q1); }
    else         { atomicAdd(&g_c4sn[jn], v1); atomicAdd(&g_c4qn[jn], q1); }
}

// ===== tail: thresholds (from counters) + ternary pack + FC2 + prelu + scale =====
__global__ void __launch_bounds__(256) k_tail(const float* __restrict__ fp0,
                                              const float* __restrict__ fg1,
                                              const float* __restrict__ fb1,
                                              const float* __restrict__ fw1,
                                              const float* __restrict__ fp1,
                                              const float* __restrict__ scale,
                                              float* __restrict__ out) {
    __shared__ float st[1024];
    __shared__ unsigned char sfl[1024];
    __shared__ unsigned sP[32], sNZ[32], sW[320];
    int n = blockIdx.x;
    int tid = threadIdx.x;
    float a = fp0[0];
    for (int f = tid; f < 1024; f += 256) {
        thresh_from_sums((double)g_c4sp[f], (double)g_c4sn[f],
                         (double)g_c4qp[f], (double)g_c4qn[f],
                         (double)a, 128.0, fg1[f], fb1[f], &st[f], &sfl[f]);
    }
    for (int id = tid; id < 320; id += 256) {
        int k = id >> 5, w = id & 31;
        const float* src = fw1 + k * 1024 + w * 32;
        unsigned v = 0;
#pragma unroll
        for (int i = 0; i < 32; i++)
            if (src[i] > 0.f) v |= 1u << i;
        sW[id] = v;
    }
    __syncthreads();
    if (tid < 32) {
        unsigned v = 0, nz = 0;
        const short* src = g_b1 + n * 1024 + tid * 32;
#pragma unroll
        for (int i = 0; i < 32; i++) {
            float val = preluf((float)src[i], a);
            float t = st[tid * 32 + i];
            if (val != t) {
                nz |= 1u << i;
                if ((val > t) != (sfl[tid * 32 + i] != 0)) v |= 1u << i;
            }
        }
        sP[tid] = v; sNZ[tid] = nz;
    }
    __syncthreads();
    if (tid < 10) {
        int acc = 0, knz = 0;
#pragma unroll
        for (int w = 0; w < 32; w++) {
            unsigned nz = sNZ[w];
            knz += __popc(nz);
            acc += __popc((sP[w] ^ sW[tid * 32 + w]) & nz);
        }
        float v = (float)(knz - 2 * acc);
        v = preluf(v, fp1[0]);
        out[n * 10 + tid] = v * scale[0];
    }
}

// ======================= launch =======================
extern "C" void kernel_launch(void* const* d_in, const int* in_sizes, int n_in,
                              void* d_out, int out_size) {
    const float* x   = (const float*)d_in[0];
    const float* cg0 = (const float*)d_in[1];
    const float* cb0 = (const float*)d_in[2];
    const float* cw0 = (const float*)d_in[3];
    const float* cp0 = (const float*)d_in[4];
    const float* cg1 = (const float*)d_in[5];
    const float* cb1 = (const float*)d_in[6];
    const float* cw1 = (const float*)d_in[7];
    const float* cp1 = (const float*)d_in[8];
    const float* cg2 = (const float*)d_in[9];
    const float* cb2 = (const float*)d_in[10];
    const float* cw2 = (const float*)d_in[11];
    const float* cp2 = (const float*)d_in[12];
    const float* fg0 = (const float*)d_in[13];
    const float* fb0 = (const float*)d_in[14];
    const float* fw0 = (const float*)d_in[15];
    const float* fp0 = (const float*)d_in[16];
    const float* fg1 = (const float*)d_in[17];
    const float* fb1 = (const float*)d_in[18];
    const float* fw1 = (const float*)d_in[19];
    const float* fp1 = (const float*)d_in[20];
    const float* scl = (const float*)d_in[21];
    float* out = (float*)d_out;

    k_stats_x<<<dim3(128, 3), 256>>>(x);
    k_conv1<<<961, 128>>>(x, cw0, cg0, cb0);

    k_stats1_w2<<<137, 256>>>(cw1);
    k_conv2f<<<dim3(14, 128), 256>>>(cp0, cg1, cb1);

    k_pack2<<<428, 128>>>(cp1, cg2, cb2, cw2);
    k_conv3f<<<dim3(12, 128, 4), 128>>>();

    k_stats3_fw0<<<2592, 256>>>(cp2, fg0, fb0, fw0);
    k_pack3<<<288, 256>>>(cp2);
    k_fc1<<<dim3(2, 64), 512>>>();

    k_tail<<<128, 256>>>(fp0, fg1, fb1, fw1, fp1, scl, out);
}

// round 17
// speedup vs baseline: 1.3128x; 1.3128x over previous
#include <cuda_runtime.h>
#include <cstdint>
#include <cfloat>

#define BN_EPS 1e-5f

// ======================= device global scratch =======================
__device__ double g_dsum[512], g_dsq[512];

// integer stat accumulators (zeroed by k_stats_x block 0)
__device__ int                g_c1sp[128], g_c1sn[128];
__device__ unsigned long long g_c1qp[128], g_c1qn[128];
__device__ int                g_c2sp[256], g_c2sn[256];
__device__ unsigned long long g_c2qp[256], g_c2qn[256];
__device__ int                g_c4sp[1024], g_c4sn[1024];
__device__ unsigned long long g_c4qp[1024], g_c4qn[1024];

__device__ float g_t3[18432]; __device__ int g_f3[18432];

__device__ uint4    g_W2p[256 * 9];
__device__ uint4    g_W3p[4 * 18 * 128];   // [ocquarter][k(tap*2+half)][oc_local]
__device__ unsigned g_FW0pT[576 * 1024];

__device__ signed char g_a1[128 * 31 * 31 * 128];  // pooled conv1 ints, NHWC
__device__ short       g_a2[128 * 14 * 14 * 256];  // pooled conv2 ints, NHWC
__device__ uint4       g_P2[128 * 14 * 14 * 2];    // packed signs, 256 bits/pixel
__device__ short       g_p3[128 * 18432];          // pooled conv3 ints [n][f]
__device__ unsigned    g_P3[128 * 576];            // ternary sign plane
__device__ unsigned    g_P3nz[128 * 576];          // ternary nonzero mask
__device__ short       g_b1[128 * 1024];           // fc1 ints

// ======================= helpers =======================
__device__ __forceinline__ unsigned csa_s(unsigned a, unsigned b, unsigned c) {
    return a ^ b ^ c;
}
__device__ __forceinline__ unsigned csa_c(unsigned a, unsigned b, unsigned c) {
    return (a & b) | (c & (a | b));
}
__device__ __forceinline__ uint4 xor4(uint4 a, uint4 b) {
    return make_uint4(a.x ^ b.x, a.y ^ b.y, a.z ^ b.z, a.w ^ b.w);
}

// popcount of 12 words (3 pre-XORed uint4) via CSA tree: 5 POPC instead of 12
__device__ __forceinline__ int popc12c(uint4 a, uint4 b, uint4 c) {
    unsigned s0 = csa_s(a.x, a.y, a.z), c0 = csa_c(a.x, a.y, a.z);
    unsigned s1 = csa_s(a.w, b.x, b.y), c1 = csa_c(a.w, b.x, b.y);
    unsigned s2 = csa_s(b.z, b.w, c.x), c2 = csa_c(b.z, b.w, c.x);
    unsigned s3 = csa_s(c.y, c.z, c.w), c3 = csa_c(c.y, c.z, c.w);
    unsigned S0 = csa_s(s0, s1, s2),   C4 = csa_c(s0, s1, s2);
    unsigned S5 = csa_s(c0, c1, c2),   C5 = csa_c(c0, c1, c2);
    unsigned S6 = csa_s(S5, c3, C4),   C6 = csa_c(S5, c3, C4);
    return __popc(S0) + __popc(s3) + 2 * __popc(S6) + 4 * (__popc(C5) + __popc(C6));
}

// popcount of 24 words (6 pre-XORed uint4) via CSA tree: 6 POPC instead of 24
__device__ __forceinline__ int popc24c(uint4 a, uint4 b, uint4 c, uint4 d, uint4 e, uint4 f) {
    unsigned s0 = csa_s(a.x, a.y, a.z), c0 = csa_c(a.x, a.y, a.z);
    unsigned s1 = csa_s(a.w, b.x, b.y), c1 = csa_c(a.w, b.x, b.y);
    unsigned s2 = csa_s(b.z, b.w, c.x), c2 = csa_c(b.z, b.w, c.x);
    unsigned s3 = csa_s(c.y, c.z, c.w), c3 = csa_c(c.y, c.z, c.w);
    unsigned s4 = csa_s(d.x, d.y, d.z), c4 = csa_c(d.x, d.y, d.z);
    unsigned s5 = csa_s(d.w, e.x, e.y), c5 = csa_c(d.w, e.x, e.y);
    unsigned s6 = csa_s(e.z, e.w, f.x), c6 = csa_c(e.z, e.w, f.x);
    unsigned s7 = csa_s(f.y, f.z, f.w), c7 = csa_c(f.y, f.z, f.w);
    unsigned S0 = csa_s(s0, s1, s2), C0 = csa_c(s0, s1, s2);
    unsigned S1 = csa_s(s3, s4, s5), C1 = csa_c(s3, s4, s5);
    unsigned S2 = csa_s(S0, S1, s6), C2 = csa_c(S0, S1, s6);
    unsigned A0 = csa_s(c0, c1, c2), B0 = csa_c(c0, c1, c2);
    unsigned A1 = csa_s(c3, c4, c5), B1 = csa_c(c3, c4, c5);
    unsigned A2 = csa_s(c6, c7, C0), B2 = csa_c(c6, c7, C0);
    unsigned A3 = csa_s(C1, C2, A0), B3 = csa_c(C1, C2, A0);
    unsigned A4 = csa_s(A1, A2, A3), B4 = csa_c(A1, A2, A3);
    unsigned D0 = csa_s(B0, B1, B2), E0 = csa_c(B0, B1, B2);
    unsigned D1 = csa_s(B3, B4, D0), E1 = csa_c(B3, B4, D0);
    return __popc(S2) + __popc(s7) + 2 * __popc(A4) + 4 * __popc(D1)
         + 8 * (__popc(E0) + __popc(E1));
}

__device__ __forceinline__ float preluf(float v, float a) {
    return v >= 0.0f ? v : a * v;
}

// threshold from integer pos/neg sums (exact fp64); bb==0 fast path is exact
__device__ __forceinline__ void thresh_from_sums(double sp, double sn, double qp, double qn,
                                                 double a, double N, float g, float bb,
                                                 float* t, unsigned char* f) {
    if (g != 0.0f) {
        double m = (sp + a * sn) / N;
        if (bb == 0.0f) {
            *t = (float)m;
        } else {
            double q = (qp + a * a * qn) / N;
            double var = q - m * m;
            if (var < 0.) var = 0.;
            *t = (float)(m - (double)bb * sqrt(var + (double)BN_EPS) / (double)g);
        }
        *f = (g < 0.0f) ? 1 : 0;
    } else {
        *t = (bb > 0.0f) ? -FLT_MAX : FLT_MAX;
        *f = 0;
    }
}

// ======================= layer 0: input BN stats (fp64) + counter zeroing =========
__global__ void k_stats_x(const float* __restrict__ x) {
    __shared__ double ss[256], sq[256];
    int n = blockIdx.x, c = blockIdx.y, t = threadIdx.x;
    if (n == 0 && c == 0) {
        if (t < 128) { g_c1sp[t] = 0; g_c1sn[t] = 0; g_c1qp[t] = 0; g_c1qn[t] = 0; }
        g_c2sp[t] = 0; g_c2sn[t] = 0; g_c2qp[t] = 0; g_c2qn[t] = 0;
        for (int i = t; i < 1024; i += 256) {
            g_c4sp[i] = 0; g_c4sn[i] = 0; g_c4qp[i] = 0; g_c4qn[i] = 0;
        }
    }
    const float* p = x + (n * 3 + c) * 4096;
    double s = 0., q = 0.;
    for (int i = t; i < 4096; i += 256) {
        double v = (double)p[i];
        s += v; q += v * v;
    }
    ss[t] = s; sq[t] = q;
    __syncthreads();
    for (int o = 128; o > 0; o >>= 1) {
        if (t < o) { ss[t] += ss[t + o]; sq[t] += sq[t + o]; }
        __syncthreads();
    }
    if (t == 0) { g_dsum[c * 128 + n] = ss[0]; g_dsq[c * 128 + n] = sq[0]; }
}

// ======================= conv1 (3->128, 64->62, pool->31) =======================
__global__ void __launch_bounds__(128) k_conv1(const float* __restrict__ x,
                                               const float* __restrict__ cw0,
                                               const float* __restrict__ cg0,
                                               const float* __restrict__ cb0) {
    __shared__ unsigned sW[128];
    __shared__ float stc[3];
    __shared__ int sfc[3];
    int tid = threadIdx.x;
    {
        unsigned m = 0;
        const float* wp = cw0 + tid * 27;
#pragma unroll
        for (int i = 0; i < 27; i++)
            if (wp[i] > 0.f) m |= 1u << i;
        sW[tid] = m;
    }
    if (tid < 3) {
        double s = 0., q = 0.;
        for (int b = 0; b < 128; b++) { s += g_dsum[tid * 128 + b]; q += g_dsq[tid * 128 + b]; }
        double N = 524288.0;
        double m = s / N;
        double v = q / N - m * m;
        if (v < 0.) v = 0.;
        float g = cg0[tid], bb = cb0[tid];
        if (g != 0.0f) {
            stc[tid] = (float)(m - (double)bb * sqrt(v + (double)BN_EPS) / (double)g);
            sfc[tid] = (g < 0.0f) ? 1 : 0;
        } else {
            stc[tid] = (bb > 0.0f) ? -FLT_MAX : FLT_MAX;
            sfc[tid] = 0;
        }
    }
    __syncthreads();

    int idx = blockIdx.x * 128 + tid;           // < 123008
    int n = idx / 961, r = idx % 961, py = r / 31, px = r % 31;

    unsigned m[4] = {0, 0, 0, 0};
#pragma unroll
    for (int c = 0; c < 3; c++) {
        float tc = stc[c];
        int fc = sfc[c];
        const float2* xp2 = (const float2*)(x + ((n * 3 + c) * 64 + 2 * py) * 64 + 2 * px);
#pragma unroll
        for (int rr = 0; rr < 4; rr++) {
            float2 ab = xp2[rr * 32];
            float2 cd = xp2[rr * 32 + 1];
            float vv[4] = {ab.x, ab.y, cd.x, cd.y};
#pragma unroll
            for (int cc = 0; cc < 4; cc++) {
                unsigned b = ((vv[cc] > tc) != (fc != 0)) ? 1u : 0u;
#pragma unroll
                for (int dy = 0; dy < 2; dy++) {
#pragma unroll
                    for (int dx = 0; dx < 2; dx++) {
                        int ky = rr - dy, kx = cc - dx;
                        if (ky >= 0 && ky < 3 && kx >= 0 && kx < 3)
                            m[dy * 2 + dx] |= b << (c * 9 + ky * 3 + kx);
                    }
                }
            }
        }
    }
    unsigned* outw = reinterpret_cast<unsigned*>(g_a1) + (size_t)idx * 32;
#pragma unroll 4
    for (int oc4 = 0; oc4 < 32; oc4++) {
        unsigned pk = 0;
#pragma unroll
        for (int s = 0; s < 4; s++) {
            unsigned wv = sW[oc4 * 4 + s];
            int p0 = __popc(m[0] ^ wv), p1 = __popc(m[1] ^ wv);
            int p2 = __popc(m[2] ^ wv), p3 = __popc(m[3] ^ wv);
            int mn = min(min(p0, p1), min(p2, p3));
            int p = 27 - 2 * mn;
            pk |= ((unsigned)(unsigned char)(signed char)p) << (8 * s);
        }
        outw[oc4] = pk;
    }
}

// ======== stats over a1 (atomic to global) fused with pack_w2 =========
__global__ void __launch_bounds__(256) k_stats1_w2(const float* __restrict__ cw1) {
    if (blockIdx.x >= 128) {
        int tap = blockIdx.x - 128;        // 0..8
        int oc = threadIdx.x;              // 0..255
        int ky = tap / 3, kx = tap % 3;
        unsigned v[4] = {0, 0, 0, 0};
        for (int c = 0; c < 128; c++)
            if (cw1[((oc * 128 + c) * 3 + ky) * 3 + kx] > 0.f) v[c >> 5] |= 1u << (c & 31);
        g_W2p[oc * 9 + tap] = make_uint4(v[0], v[1], v[2], v[3]);
        return;
    }
    __shared__ int ssp[128], ssn[128], sqp[128], sqn[128];
    int tid = threadIdx.x, b = blockIdx.x;
    if (tid < 128) { ssp[tid] = 0; ssn[tid] = 0; sqp[tid] = 0; sqn[tid] = 0; }
    __syncthreads();
    int c4 = tid & 31, h = tid >> 5;
    const unsigned* aw = reinterpret_cast<const unsigned*>(g_a1);
    int sp[4] = {0,0,0,0}, sn[4] = {0,0,0,0}, qp[4] = {0,0,0,0}, qn[4] = {0,0,0,0};
    for (int i = h; i < 961; i += 8) {
        unsigned wd = aw[(size_t)(b * 961 + i) * 32 + c4];
#pragma unroll
        for (int k = 0; k < 4; k++) {
            int p = (int)(signed char)(wd >> (8 * k));
            int q = p * p;
            if (p >= 0) { sp[k] += p; qp[k] += q; }
            else        { sn[k] += p; qn[k] += q; }
        }
    }
#pragma unroll
    for (int k = 0; k < 4; k++) {
        atomicAdd(&ssp[c4 * 4 + k], sp[k]);
        atomicAdd(&ssn[c4 * 4 + k], sn[k]);
        atomicAdd(&sqp[c4 * 4 + k], qp[k]);
        atomicAdd(&sqn[c4 * 4 + k], qn[k]);
    }
    __syncthreads();
    if (tid < 128) {
        atomicAdd(&g_c1sp[tid], ssp[tid]);
        atomicAdd(&g_c1sn[tid], ssn[tid]);
        atomicAdd(&g_c1qp[tid], (unsigned long long)sqp[tid]);
        atomicAdd(&g_c1qn[tid], (unsigned long long)sqn[tid]);
    }
}

// ====== conv2 (128->256), pack fused, CSA popcount, stats2 epilogue fused ======
#define C2ROW(A0, A1, WB) \
    A0 += popc12c(xor4(t0, w[WB]), xor4(t1, w[(WB)+1]), xor4(t2, w[(WB)+2])); \
    A1 += popc12c(xor4(t1, w[WB]), xor4(t2, w[(WB)+1]), xor4(t3, w[(WB)+2]));
#define C2LOAD(RR) \
    t0 = sIn[RR][base]; t1 = sIn[RR][base+1]; t2 = sIn[RR][base+2]; t3 = sIn[RR][base+3];

__global__ void __launch_bounds__(256, 3) k_conv2f(const float* __restrict__ cp0,
                                                   const float* __restrict__ cg1,
                                                   const float* __restrict__ cb1) {
    __shared__ uint4 sIn[4][31];
    __shared__ float st[128];
    __shared__ unsigned char sfl[128];
    int py = blockIdx.x, n = blockIdx.y, tid = threadIdx.x;
    float a = cp0[0];
    if (tid < 128) {
        thresh_from_sums((double)g_c1sp[tid], (double)g_c1sn[tid],
                         (double)g_c1qp[tid], (double)g_c1qn[tid],
                         (double)a, 123008.0, cg1[tid], cb1[tid], &st[tid], &sfl[tid]);
    }
    unsigned* sw = reinterpret_cast<unsigned*>(sIn);
    for (int i = tid; i < 496; i += 256) sw[i] = 0;
    __syncthreads();

    const unsigned* aw = reinterpret_cast<const unsigned*>(g_a1);
    for (int i = tid; i < 124 * 32; i += 256) {
        int p = i >> 5, wv = i & 31;
        int r = p / 31, cc = p % 31;
        unsigned wd = aw[(size_t)((n * 31 + 2 * py + r) * 31 + cc) * 32 + wv];
        unsigned bits = 0;
#pragma unroll
        for (int k = 0; k < 4; k++) {
            int c = wv * 4 + k;
            float v = preluf((float)(signed char)(wd >> (8 * k)), a);
            if ((v > st[c]) != (sfl[c] != 0)) bits |= 1u << k;
        }
        atomicOr(&sw[(r * 31 + cc) * 4 + (wv >> 3)], bits << ((wv & 7) * 4));
    }
    uint4 w[9];
#pragma unroll
    for (int k = 0; k < 9; k++) w[k] = g_W2p[tid * 9 + k];
    __syncthreads();

    short* op = g_a2 + (size_t)((n * 14 + py) * 14) * 256 + tid;
    int lsp = 0, lsn = 0, lqp = 0, lqn = 0;
    for (int px = 0; px < 14; px++) {
        int base = 2 * px;
        int a00 = 0, a01 = 0, a10 = 0, a11 = 0;
        uint4 t0, t1, t2, t3;
        C2LOAD(0); C2ROW(a00, a01, 0);
        C2LOAD(1); C2ROW(a00, a01, 3); C2ROW(a10, a11, 0);
        C2LOAD(2); C2ROW(a00, a01, 6); C2ROW(a10, a11, 3);
        C2LOAD(3); C2ROW(a10, a11, 6);
        int best = min(min(a00, a01), min(a10, a11));
        int v = 1152 - 2 * best;
        op[px * 256] = (short)v;
        int q = v * v;
        if (v >= 0) { lsp += v; lqp += q; } else { lsn += v; lqn += q; }
    }
    atomicAdd(&g_c2sp[tid], lsp);
    atomicAdd(&g_c2sn[tid], lsn);
    atomicAdd(&g_c2qp[tid], (unsigned long long)lqp);
    atomicAdd(&g_c2qn[tid], (unsigned long long)lqn);
}

// ========== pack a2 -> P2 (shared transpose, coalesced) + pack_w3 rider ==========
__global__ void __launch_bounds__(128) k_pack2(const float* __restrict__ cp1,
                                               const float* __restrict__ cg2,
                                               const float* __restrict__ cb2,
                                               const float* __restrict__ cw2) {
    if (blockIdx.x >= 392) {
        int vb = blockIdx.x - 392;        // 0..35
        int tap = vb % 9, zq = vb / 9;    // zq 0..3
        int oc = zq * 128 + threadIdx.x;
        int ky = tap / 3, kx = tap % 3;
        for (int h = 0; h < 2; h++) {
            unsigned v[4] = {0, 0, 0, 0};
            for (int i = 0; i < 128; i++) {
                int c = h * 128 + i;
                if (cw2[((oc * 256 + c) * 3 + ky) * 3 + kx] > 0.f) v[i >> 5] |= 1u << (i & 31);
            }
            g_W3p[(zq * 18 + (tap * 2 + h)) * 128 + threadIdx.x] =
                make_uint4(v[0], v[1], v[2], v[3]);
        }
        return;
    }
    __shared__ unsigned sh[64][129];
    __shared__ float st[256];
    __shared__ unsigned char sfl[256];
    int tid = threadIdx.x;
    float a = cp1[0];
    {
        double ad = (double)a;
        for (int j = tid; j < 256; j += 128) {
            thresh_from_sums((double)g_c2sp[j], (double)g_c2sn[j],
                             (double)g_c2qp[j], (double)g_c2qn[j],
                             ad, 25088.0, cg2[j], cb2[j], &st[j], &sfl[j]);
        }
    }
    const unsigned* aw = reinterpret_cast<const unsigned*>(g_a2);
    size_t base = (size_t)blockIdx.x * 64 * 128;
    for (int j = tid; j < 8192; j += 128) sh[j >> 7][j & 127] = aw[base + j];
    __syncthreads();
    int pix = tid & 63, half = tid >> 6;
    unsigned wout[4];
#pragma unroll
    for (int oj = 0; oj < 4; oj++) {
        unsigned wd = 0;
#pragma unroll
        for (int i = 0; i < 32; i++) {
            int ch = half * 128 + oj * 32 + i;
            unsigned word = sh[pix][ch >> 1];
            int p = (ch & 1) ? (int)(short)(word >> 16) : (int)(short)(word & 0xFFFFu);
            float v = preluf((float)p, a);
            unsigned bit = ((v > st[ch]) != (sfl[ch] != 0)) ? 1u : 0u;
            wd |= bit << i;
        }
        wout[oj] = wd;
    }
    g_P2[((size_t)blockIdx.x * 64 + pix) * 2 + half] =
        make_uint4(wout[0], wout[1], wout[2], wout[3]);
}

// ============ conv3 (256->512), ky-outer, low-reg, reads packed P2 ============
__global__ void __launch_bounds__(128) k_conv3f() {
    __shared__ uint4 sIn[4][14][2];
    int py = blockIdx.x, n = blockIdx.y, zq = blockIdx.z, tid = threadIdx.x;
    int oc = zq * 128 + tid;
    for (int i = tid; i < 112; i += 128) {
        int h = i & 1, t_ = i >> 1;
        int r = t_ / 14, cc = t_ % 14;
        sIn[r][cc][h] = g_P2[((n * 14 + 2 * py + r) * 14 + cc) * 2 + h];
    }
    __syncthreads();

    int A00[6] = {0,0,0,0,0,0}, A01[6] = {0,0,0,0,0,0};
    int A10[6] = {0,0,0,0,0,0}, A11[6] = {0,0,0,0,0,0};

#pragma unroll
    for (int ky = 0; ky < 3; ky++) {
        uint4 w0a = g_W3p[(zq * 18 + (ky * 3 + 0) * 2 + 0) * 128 + tid];
        uint4 w0b = g_W3p[(zq * 18 + (ky * 3 + 0) * 2 + 1) * 128 + tid];
        uint4 w1a = g_W3p[(zq * 18 + (ky * 3 + 1) * 2 + 0) * 128 + tid];
        uint4 w1b = g_W3p[(zq * 18 + (ky * 3 + 1) * 2 + 1) * 128 + tid];
        uint4 w2a = g_W3p[(zq * 18 + (ky * 3 + 2) * 2 + 0) * 128 + tid];
        uint4 w2b = g_W3p[(zq * 18 + (ky * 3 + 2) * 2 + 1) * 128 + tid];
#pragma unroll
        for (int px = 0; px < 6; px++) {
            int base = 2 * px;
            uint4 t0a, t0b, t1a, t1b, t2a, t2b, t3a, t3b;
            t0a = sIn[ky][base][0];     t0b = sIn[ky][base][1];
            t1a = sIn[ky][base + 1][0]; t1b = sIn[ky][base + 1][1];
            t2a = sIn[ky][base + 2][0]; t2b = sIn[ky][base + 2][1];
            t3a = sIn[ky][base + 3][0]; t3b = sIn[ky][base + 3][1];
            A00[px] += popc24c(xor4(t0a, w0a), xor4(t0b, w0b),
                               xor4(t1a, w1a), xor4(t1b, w1b),
                               xor4(t2a, w2a), xor4(t2b, w2b));
            A01[px] += popc24c(xor4(t1a, w0a), xor4(t1b, w0b),
                               xor4(t2a, w1a), xor4(t2b, w1b),
                               xor4(t3a, w2a), xor4(t3b, w2b));
            t0a = sIn[ky + 1][base][0];     t0b = sIn[ky + 1][base][1];
            t1a = sIn[ky + 1][base + 1][0]; t1b = sIn[ky + 1][base + 1][1];
            t2a = sIn[ky + 1][base + 2][0]; t2b = sIn[ky + 1][base + 2][1];
            t3a = sIn[ky + 1][base + 3][0]; t3b = sIn[ky + 1][base + 3][1];
            A10[px] += popc24c(xor4(t0a, w0a), xor4(t0b, w0b),
                               xor4(t1a, w1a), xor4(t1b, w1b),
                               xor4(t2a, w2a), xor4(t2b, w2b));
            A11[px] += popc24c(xor4(t1a, w0a), xor4(t1b, w0b),
                               xor4(t2a, w1a), xor4(t2b, w1b),
                               xor4(t3a, w2a), xor4(t3b, w2b));
        }
    }

    short* op = g_p3 + (size_t)n * 18432 + oc * 36 + py * 6;
#pragma unroll
    for (int px = 0; px < 6; px++) {
        int best = min(min(A00[px], A01[px]), min(A10[px], A11[px]));
        op[px] = (short)(2304 - 2 * best);
    }
}

// ======== BN1d stats over p3 (coalesced) fused with pack_fw0 =========
__global__ void __launch_bounds__(256) k_stats3_fw0(const float* __restrict__ cp2,
                                                    const float* __restrict__ fg,
                                                    const float* __restrict__ fb,
                                                    const float* __restrict__ fw0) {
    if (blockIdx.x >= 288) {
        int id = (blockIdx.x - 288) * 256 + threadIdx.x;   // < 589824
        int j = id / 576, w = id % 576;
        const float* src = fw0 + j * 18432 + w * 32;
        unsigned v = 0;
#pragma unroll
        for (int i = 0; i < 32; i++)
            if (src[i] > 0.f) v |= 1u << i;
        g_FW0pT[w * 1024 + j] = v;
        return;
    }
    __shared__ float ss[4][64], sq2[4][64];
    int tid = threadIdx.x;
    int f0 = blockIdx.x * 64;
    int fl = tid & 63, nq = tid >> 6;
    float a = cp2[0];
    float s = 0.f, q = 0.f;
    for (int n = nq; n < 128; n += 4) {
        float v = preluf((float)g_p3[(size_t)n * 18432 + f0 + fl], a);
        s += v; q += v * v;
    }
    ss[nq][fl] = s; sq2[nq][fl] = q;
    __syncthreads();
    if (tid < 64) {
        int f = f0 + tid;
        s = ss[0][tid] + ss[1][tid] + ss[2][tid] + ss[3][tid];
        q = sq2[0][tid] + sq2[1][tid] + sq2[2][tid] + sq2[3][tid];
        float m = s / 128.f;
        float var = q / 128.f - m * m;
        var = fmaxf(var, 0.0f);
        float g = fg[f], bb = fb[f];
        if (g != 0.0f) {
            g_t3[f] = (bb == 0.0f) ? m : (m - bb * sqrtf(var + BN_EPS) / g);
            g_f3[f] = (g < 0.0f) ? 1 : 0;
        } else { g_t3[f] = (bb > 0.0f) ? -FLT_MAX : FLT_MAX; g_f3[f] = 0; }
    }
}

// ternary pack: tie (val == t) -> nz bit cleared
__global__ void k_pack3(const float* __restrict__ cp2) {
    int id = blockIdx.x * 256 + threadIdx.x;  // < 73728
    int n = id / 576, w = id % 576;
    float a = cp2[0];
    const short* src = g_p3 + (size_t)n * 18432 + w * 32;
    unsigned v = 0, nz = 0;
#pragma unroll
    for (int i = 0; i < 32; i++) {
        float val = (float)src[i];
        val = preluf(val, a);
        float t = g_t3[w * 32 + i];
        if (val != t) {
            nz |= 1u << i;
            if ((val > t) != (g_f3[w * 32 + i] != 0)) v |= 1u << i;
        }
    }
    g_P3[n * 576 + w] = v;
    g_P3nz[n * 576 + w] = nz;
}

// ============= FC1 (18432 -> 1024), ternary-aware, + stats4 epilogue =============
__global__ void __launch_bounds__(512) k_fc1() {
    __shared__ unsigned sS[2][576], sN[2][576];
    __shared__ int sK[2];
    int tid = threadIdx.x;
    int n0 = blockIdx.y * 2;
    int jn = blockIdx.x * 512 + tid;
    if (tid < 2) sK[tid] = 0;
    __syncthreads();
    for (int j = tid; j < 1152; j += 512) {
        int s = (j >= 576) ? 1 : 0;
        int w = j - s * 576;
        unsigned sg = g_P3[(n0 + s) * 576 + w];
        unsigned nz = g_P3nz[(n0 + s) * 576 + w];
        sS[s][w] = sg; sN[s][w] = nz;
        atomicAdd(&sK[s], __popc(nz));
    }
    __syncthreads();
    int a0 = 0, a1 = 0;
#pragma unroll 8
    for (int w = 0; w < 576; w++) {
        unsigned wt = g_FW0pT[w * 1024 + jn];
        a0 += __popc((sS[0][w] ^ wt) & sN[0][w]);
        a1 += __popc((sS[1][w] ^ wt) & sN[1][w]);
    }
    int v0 = sK[0] - 2 * a0;
    int v1 = sK[1] - 2 * a1;
    g_b1[n0 * 1024 + jn] = (short)v0;
    g_b1[(n0 + 1) * 1024 + jn] = (short)v1;
    unsigned long long q0 = (unsigned long long)((long long)v0 * v0);
    unsigned long long q1 = (unsigned long long)((long long)v1 * v1);
    if (v0 >= 0) { atomicAdd(&g_c4sp[jn], v0); atomicAdd(&g_c4qp[jn], q0); }
    else         { atomicAdd(&g_c4sn[jn], v0); atomicAdd(&g_c4qn[jn], q0); }
    if (v1 >= 0) { atomicAdd(&g_c4sp[jn], v1); atomicAdd(&g_c4qp[jn], q1); }
    else         { atomicAdd(&g_c4sn[jn], v1); atomicAdd(&g_c4qn[jn], q1); }
}

// ===== tail: thresholds (from counters) + ternary pack + FC2 + prelu + scale =====
__global__ void __launch_bounds__(256) k_tail(const float* __restrict__ fp0,
                                              const float* __restrict__ fg1,
                                              const float* __restrict__ fb1,
                                              const float* __restrict__ fw1,
                                              const float* __restrict__ fp1,
                                              const float* __restrict__ scale,
                                              float* __restrict__ out) {
    __shared__ float st[1024];
    __shared__ unsigned char sfl[1024];
    __shared__ unsigned sP[32], sNZ[32], sW[320];
    int n = blockIdx.x;
    int tid = threadIdx.x;
    float a = fp0[0];
    for (int f = tid; f < 1024; f += 256) {
        thresh_from_sums((double)g_c4sp[f], (double)g_c4sn[f],
                         (double)g_c4qp[f], (double)g_c4qn[f],
                         (double)a, 128.0, fg1[f], fb1[f], &st[f], &sfl[f]);
    }
    for (int id = tid; id < 320; id += 256) {
        int k = id >> 5, w = id & 31;
        const float* src = fw1 + k * 1024 + w * 32;
        unsigned v = 0;
#pragma unroll
        for (int i = 0; i < 32; i++)
            if (src[i] > 0.f) v |= 1u << i;
        sW[id] = v;
    }
    __syncthreads();
    if (tid < 32) {
        unsigned v = 0, nz = 0;
        const short* src = g_b1 + n * 1024 + tid * 32;
#pragma unroll
        for (int i = 0; i < 32; i++) {
            float val = preluf((float)src[i], a);
            float t = st[tid * 32 + i];
            if (val != t) {
                nz |= 1u << i;
                if ((val > t) != (sfl[tid * 32 + i] != 0)) v |= 1u << i;
            }
        }
        sP[tid] = v; sNZ[tid] = nz;
    }
    __syncthreads();
    if (tid < 10) {
        int acc = 0, knz = 0;
#pragma unroll
        for (int w = 0; w < 32; w++) {
            unsigned nz = sNZ[w];
            knz += __popc(nz);
            acc += __popc((sP[w] ^ sW[tid * 32 + w]) & nz);
        }
        float v = (float)(knz - 2 * acc);
        v = preluf(v, fp1[0]);
        out[n * 10 + tid] = v * scale[0];
    }
}

// ======================= launch =======================
extern "C" void kernel_launch(void* const* d_in, const int* in_sizes, int n_in,
                              void* d_out, int out_size) {
    const float* x   = (const float*)d_in[0];
    const float* cg0 = (const float*)d_in[1];
    const float* cb0 = (const float*)d_in[2];
    const float* cw0 = (const float*)d_in[3];
    const float* cp0 = (const float*)d_in[4];
    const float* cg1 = (const float*)d_in[5];
    const float* cb1 = (const float*)d_in[6];
    const float* cw1 = (const float*)d_in[7];
    const float* cp1 = (const float*)d_in[8];
    const float* cg2 = (const float*)d_in[9];
    const float* cb2 = (const float*)d_in[10];
    const float* cw2 = (const float*)d_in[11];
    const float* cp2 = (const float*)d_in[12];
    const float* fg0 = (const float*)d_in[13];
    const float* fb0 = (const float*)d_in[14];
    const float* fw0 = (const float*)d_in[15];
    const float* fp0 = (const float*)d_in[16];
    const float* fg1 = (const float*)d_in[17];
    const float* fb1 = (const float*)d_in[18];
    const float* fw1 = (const float*)d_in[19];
    const float* fp1 = (const float*)d_in[20];
    const float* scl = (const float*)d_in[21];
    float* out = (float*)d_out;

    k_stats_x<<<dim3(128, 3), 256>>>(x);
    k_conv1<<<961, 128>>>(x, cw0, cg0, cb0);

    k_stats1_w2<<<137, 256>>>(cw1);
    k_conv2f<<<dim3(14, 128), 256>>>(cp0, cg1, cb1);

    k_pack2<<<428, 128>>>(cp1, cg2, cb2, cw2);
    k_conv3f<<<dim3(6, 128, 4), 128>>>();

    k_stats3_fw0<<<2592, 256>>>(cp2, fg0, fb0, fw0);
    k_pack3<<<288, 256>>>(cp2);
    k_fc1<<<dim3(2, 64), 512>>>();

    k_tail<<<128, 256>>>(fp0, fg1, fb1, fw1, fp1, scl, out);
}